// round 3
// baseline (speedup 1.0000x reference)
#include <cuda_runtime.h>
#include <cuda_fp16.h>
#include <cstdint>

#define NN   1546
#define ND   1373
#define KF   1546
#define HEADS 8
#define EMAX 210000
#define EPSV 1e-12f
#define TAOV 0.4f

// ------------------- scratch (device globals; no allocs allowed) -------------------
__device__ __align__(16) float  g_fs  [NN * 512];   // feat_src  [N, 8*64] fp32
__device__ __align__(16) __half g_fs16[NN * 512];   // feat_src fp16 (edge phase)
__device__ __align__(16) float  g_res [NN * 512];   // resval
__device__ __align__(16) float  g_attn[NN * 512];   // ft_attn
__device__ __align__(16) __half g_sn16[NN * 64];    // sloc normalized, fp16
__device__ __align__(16) __half g_tn16[NN * 64];    // topo normalized, fp16
__device__ float g_snorm[NN];
__device__ float g_tnorm[NN];
__device__ float g_colsq [512];
__device__ float g_rscale[512];
__device__ int   g_cnt[NN];
__device__ int   g_off[NN];
__device__ int   g_cur[NN];
__device__ int   g_order[EMAX];

// ------------------- helpers -------------------
__device__ __forceinline__ float f2tf32(float x) {
    uint32_t r;
    asm("cvt.rna.tf32.f32 %0, %1;" : "=r"(r) : "f"(x));
    return __uint_as_float(r);
}

__device__ __forceinline__ void mma_tf32(float* c, const uint32_t* a, const uint32_t* b) {
    asm volatile(
        "mma.sync.aligned.m16n8k8.row.col.f32.tf32.tf32.f32 "
        "{%0,%1,%2,%3}, {%4,%5,%6,%7}, {%8,%9}, {%0,%1,%2,%3};\n"
        : "+f"(c[0]), "+f"(c[1]), "+f"(c[2]), "+f"(c[3])
        : "r"(a[0]), "r"(a[1]), "r"(a[2]), "r"(a[3]), "r"(b[0]), "r"(b[1]));
}

// ------------------- zero scratch counters -------------------
__global__ void k_zero() {
    int i = blockIdx.x * 256 + threadIdx.x;
    if (i < NN)  g_cnt[i] = 0;
    if (i < 512) g_colsq[i] = 0.f;
}

// ------------------- tf32 GEMM: BM=128 BN=128 BK=16, 256 thr, warp tile 32x64 -------------------
#define APAD 20
#define BPAD 136

__device__ __forceinline__ void ldA2(const float* feat, int rowb, int rowEnd, int k0,
                                     int tid, float2* pa) {
#pragma unroll
    for (int j = 0; j < 4; j++) {
        int idx = tid + j * 256;
        int r = idx >> 3, c2 = idx & 7;
        int gr = rowb + r, gk = k0 + c2 * 2;
        float2 v = make_float2(0.f, 0.f);
        if (gr < rowEnd) {
            const float* p = feat + (size_t)gr * KF + gk;
            if (gk + 2 <= KF)      v = *(const float2*)p;
            else if (gk < KF)      v.x = *p;
        }
        pa[j] = v;
    }
}
__device__ __forceinline__ void ldB2(const float* W, int colb, int k0, int tid, float4* pb) {
#pragma unroll
    for (int j = 0; j < 2; j++) {
        int idx = tid + j * 256;
        int r = idx >> 5, c4 = idx & 31;
        int gk = k0 + r;
        float4 v = make_float4(0.f, 0.f, 0.f, 0.f);
        if (gk < KF) v = *(const float4*)(W + (size_t)gk * 512 + colb + c4 * 4);
        pb[j] = v;
    }
}
__device__ __forceinline__ void stA2(float* As, int tid, const float2* pa) {
#pragma unroll
    for (int j = 0; j < 4; j++) {
        int idx = tid + j * 256;
        int r = idx >> 3, c2 = idx & 7;
        As[r * APAD + c2 * 2]     = f2tf32(pa[j].x);
        As[r * APAD + c2 * 2 + 1] = f2tf32(pa[j].y);
    }
}
__device__ __forceinline__ void stB2(float* Bs, int tid, const float4* pb) {
#pragma unroll
    for (int j = 0; j < 2; j++) {
        int idx = tid + j * 256;
        int r = idx >> 5, c4 = idx & 31;
        Bs[r * BPAD + c4 * 4]     = f2tf32(pb[j].x);
        Bs[r * BPAD + c4 * 4 + 1] = f2tf32(pb[j].y);
        Bs[r * BPAD + c4 * 4 + 2] = f2tf32(pb[j].z);
        Bs[r * BPAD + c4 * 4 + 3] = f2tf32(pb[j].w);
    }
}

__global__ __launch_bounds__(256, 1) void k_gemm(const float* __restrict__ feat,
                                                 const float* __restrict__ Wp,
                                                 const float* __restrict__ Wr) {
    __shared__ float As[2][128 * APAD];
    __shared__ float Bs[2][16 * BPAD];
    int tid = threadIdx.x, lane = tid & 31, warp = tid >> 5;
    int by = blockIdx.y, bx = blockIdx.x;

    int g, rowb, rowEnd;
    if (by < 11) { g = 0; rowb = by * 128; rowEnd = ND; }
    else         { g = 1; rowb = ND + (by - 11) * 128; rowEnd = NN; }

    int cb0 = bx * 128;
    const float* W;
    float* outp;
    int colb;
    bool isFs;
    if (cb0 < 512) { W = Wp + (size_t)g * KF * 512; outp = g_fs;  colb = cb0;       isFs = true; }
    else           { W = Wr + (size_t)g * KF * 512; outp = g_res; colb = cb0 - 512; isFs = false; }

    float c[2][8][4];
#pragma unroll
    for (int i = 0; i < 2; i++)
#pragma unroll
        for (int j = 0; j < 8; j++)
#pragma unroll
            for (int k = 0; k < 4; k++) c[i][j][k] = 0.f;

    float2 pa[4];
    float4 pb[2];
    ldA2(feat, rowb, rowEnd, 0, tid, pa);
    ldB2(W, colb, 0, tid, pb);
    stA2(As[0], tid, pa);
    stB2(Bs[0], tid, pb);
    __syncthreads();

    int p = 0;
    int warpM = warp >> 1, warpN = warp & 1;
    for (int k0 = 0; k0 < KF; k0 += 16) {
        int kn = k0 + 16;
        if (kn < KF) { ldA2(feat, rowb, rowEnd, kn, tid, pa); ldB2(W, colb, kn, tid, pb); }
#pragma unroll
        for (int kk = 0; kk < 16; kk += 8) {
            uint32_t af[2][4], bf[8][2];
            int kq = kk + (lane & 3);
#pragma unroll
            for (int mt = 0; mt < 2; mt++) {
                int row = warpM * 32 + mt * 16 + (lane >> 2);
                af[mt][0] = __float_as_uint(As[p][row * APAD + kq]);
                af[mt][1] = __float_as_uint(As[p][(row + 8) * APAD + kq]);
                af[mt][2] = __float_as_uint(As[p][row * APAD + kq + 4]);
                af[mt][3] = __float_as_uint(As[p][(row + 8) * APAD + kq + 4]);
            }
#pragma unroll
            for (int nt = 0; nt < 8; nt++) {
                int col = warpN * 64 + nt * 8 + (lane >> 2);
                bf[nt][0] = __float_as_uint(Bs[p][kq * BPAD + col]);
                bf[nt][1] = __float_as_uint(Bs[p][(kq + 4) * BPAD + col]);
            }
#pragma unroll
            for (int mt = 0; mt < 2; mt++)
#pragma unroll
                for (int nt = 0; nt < 8; nt++)
                    mma_tf32(c[mt][nt], af[mt], bf[nt]);
        }
        if (kn < KF) {
            stA2(As[p ^ 1], tid, pa);
            stB2(Bs[p ^ 1], tid, pb);
            __syncthreads();
            p ^= 1;
        }
    }

#pragma unroll
    for (int mt = 0; mt < 2; mt++) {
        int row0 = rowb + warpM * 32 + mt * 16 + (lane >> 2);
#pragma unroll
        for (int nt = 0; nt < 8; nt++) {
            int col = colb + warpN * 64 + nt * 8 + (lane & 3) * 2;
            if (row0 < rowEnd) {
                *(float2*)(outp + (size_t)row0 * 512 + col) = make_float2(c[mt][nt][0], c[mt][nt][1]);
                if (isFs)
                    *(half2*)(g_fs16 + (size_t)row0 * 512 + col) = __floats2half2_rn(c[mt][nt][0], c[mt][nt][1]);
            }
            if (row0 + 8 < rowEnd) {
                *(float2*)(outp + (size_t)(row0 + 8) * 512 + col) = make_float2(c[mt][nt][2], c[mt][nt][3]);
                if (isFs)
                    *(half2*)(g_fs16 + (size_t)(row0 + 8) * 512 + col) = __floats2half2_rn(c[mt][nt][2], c[mt][nt][3]);
            }
        }
    }
}

// ------------------- ft_attn = softmax(tanh(fs @ Wprob[h])), Wprob cached in smem -------------------
#define ATTN_CH 194
__global__ __launch_bounds__(256) void k_attn(const float* __restrict__ Wprob) {
    __shared__ float Wh[4096];
    __shared__ float fsh[8][64];
    int tid = threadIdx.x, warp = tid >> 5, lane = tid & 31;
    int h = blockIdx.x & 7, chunk = blockIdx.x >> 3;
    const float* W = Wprob + h * 4096;
    for (int i = tid; i < 4096; i += 256) Wh[i] = W[i];
    __syncthreads();

    int n0 = chunk * ATTN_CH;
    int n1 = min(n0 + ATTN_CH, NN);
    for (int n = n0 + warp; n < n1; n += 8) {
        fsh[warp][lane]      = g_fs[n * 512 + h * 64 + lane];
        fsh[warp][lane + 32] = g_fs[n * 512 + h * 64 + lane + 32];
        __syncwarp();
        float a0 = 0.f, a1 = 0.f;
#pragma unroll 8
        for (int d = 0; d < 64; d++) {
            float f = fsh[warp][d];
            a0 += f * Wh[d * 64 + lane];
            a1 += f * Wh[d * 64 + lane + 32];
        }
        float t0 = tanhf(a0), t1 = tanhf(a1);
        float m = fmaxf(t0, t1);
#pragma unroll
        for (int off = 16; off; off >>= 1) m = fmaxf(m, __shfl_xor_sync(0xffffffffu, m, off));
        float e0 = __expf(t0 - m), e1 = __expf(t1 - m);
        float s = e0 + e1;
#pragma unroll
        for (int off = 16; off; off >>= 1) s += __shfl_xor_sync(0xffffffffu, s, off);
        float inv = 1.f / s;
        g_attn[n * 512 + h * 64 + lane]      = e0 * inv;
        g_attn[n * 512 + h * 64 + lane + 32] = e1 * inv;
        __syncwarp();
    }
}

// ------------------- column sq-sums of fs (axis-0 L2 norm) -------------------
__global__ void k_colsq() {
    int c = blockIdx.x * 256 + threadIdx.x;           // gridDim = (2, 64)
    int r0 = blockIdx.y * 25;
    int r1 = min(r0 + 25, NN);
    float acc = 0.f;
    for (int n = r0; n < r1; n++) {
        float v = g_fs[n * 512 + c];
        acc += v * v;
    }
    atomicAdd(&g_colsq[c], acc);
}
__global__ void k_rscale() {
    int c = blockIdx.x * 256 + threadIdx.x;
    if (c < 512) g_rscale[c] = 1.f / fmaxf(sqrtf(g_colsq[c]), EPSV);
}

// ------------------- row norms of sloc / topo -> normalized fp16 + norms -------------------
__global__ __launch_bounds__(128) void k_rownorm(const float* __restrict__ sloc,
                                                 const float* __restrict__ topo) {
    int warp = threadIdx.x >> 5, lane = threadIdx.x & 31;
    int n = blockIdx.x * 4 + warp;
    if (n >= NN) return;
    float2 sv = *(const float2*)(sloc + (size_t)n * 64 + 2 * lane);
    float2 tv = *(const float2*)(topo + (size_t)n * 64 + 2 * lane);
    float ss = sv.x * sv.x + sv.y * sv.y;
    float tt = tv.x * tv.x + tv.y * tv.y;
#pragma unroll
    for (int off = 16; off; off >>= 1) {
        ss += __shfl_xor_sync(0xffffffffu, ss, off);
        tt += __shfl_xor_sync(0xffffffffu, tt, off);
    }
    float sn = fmaxf(sqrtf(ss), EPSV), tn = fmaxf(sqrtf(tt), EPSV);
    float si = 1.f / sn, ti = 1.f / tn;
    ((half2*)(g_sn16 + (size_t)n * 64))[lane] = __floats2half2_rn(sv.x * si, sv.y * si);
    ((half2*)(g_tn16 + (size_t)n * 64))[lane] = __floats2half2_rn(tv.x * ti, tv.y * ti);
    if (lane == 0) { g_snorm[n] = sn; g_tnorm[n] = tn; }
}

// ------------------- counting sort of edges by dst -------------------
__global__ void k_hist(const int* __restrict__ dst, int E) {
    int e = blockIdx.x * 256 + threadIdx.x;
    if (e < E) atomicAdd(&g_cnt[dst[e]], 1);
}
__global__ __launch_bounds__(512) void k_scan() {
    __shared__ int sh[512];
    int t = threadIdx.x;
    int base = t * 4;
    int v0 = (base     < NN) ? g_cnt[base]     : 0;
    int v1 = (base + 1 < NN) ? g_cnt[base + 1] : 0;
    int v2 = (base + 2 < NN) ? g_cnt[base + 2] : 0;
    int v3 = (base + 3 < NN) ? g_cnt[base + 3] : 0;
    int p0 = v0, p1 = p0 + v1, p2 = p1 + v2, p3 = p2 + v3;
    sh[t] = p3;
    __syncthreads();
    for (int off = 1; off < 512; off <<= 1) {
        int x = 0;
        if (t >= off) x = sh[t - off];
        __syncthreads();
        sh[t] += x;
        __syncthreads();
    }
    int excl = sh[t] - p3;
    if (base     < NN) { g_off[base]     = excl;      g_cur[base]     = excl; }
    if (base + 1 < NN) { g_off[base + 1] = excl + p0; g_cur[base + 1] = excl + p0; }
    if (base + 2 < NN) { g_off[base + 2] = excl + p1; g_cur[base + 2] = excl + p1; }
    if (base + 3 < NN) { g_off[base + 3] = excl + p2; g_cur[base + 3] = excl + p2; }
}
__global__ void k_scatter(const int* __restrict__ dst, int E) {
    int e = blockIdx.x * 256 + threadIdx.x;
    if (e < E) {
        int pos = atomicAdd(&g_cur[dst[e]], 1);
        g_order[pos] = e;
    }
}

// ------------------- edge phase: single pass, online softmax, fp16 gathers -------------------
__global__ __launch_bounds__(256, 2) void k_edge(const float* __restrict__ sloc,
                                                 const float* __restrict__ topo,
                                                 const float* __restrict__ etw_tab,
                                                 const int* __restrict__ src,
                                                 const int* __restrict__ efeat,
                                                 float* __restrict__ out) {
    __shared__ float s_as[512];      // attn[dst] * rscale
    __shared__ float s_sd[64], s_td[64];
    __shared__ float s_accR[512], s_accS[512], s_accT[512];
    __shared__ float s_gmax[8], s_den[8], s_wmax[64];

    int n = blockIdx.x;
    int tid = threadIdx.x, warp = tid >> 5, lane = tid & 31;
    int start = g_off[n], cnt = g_cnt[n];

    for (int i = tid; i < 512; i += 256) {
        s_as[i] = g_attn[n * 512 + i] * g_rscale[i];
        s_accR[i] = 0.f; s_accS[i] = 0.f; s_accT[i] = 0.f;
    }
    if (tid < 64) {
        s_sd[tid] = __half2float(g_sn16[n * 64 + tid]);
        s_td[tid] = __half2float(g_tn16[n * 64 + tid]);
    }
    if (tid < 8) s_den[tid] = 0.f;
    __syncthreads();

    int h = lane >> 2, q = lane & 3;
    int kb = lane * 16, d0 = q * 16;
    float m = -1e30f, dsum = 0.f;
    float accR[16], accS[16], accT[16];
#pragma unroll
    for (int k = 0; k < 16; k++) { accR[k] = 0.f; accS[k] = 0.f; accT[k] = 0.f; }

    for (int i = warp; i < cnt; i += 8) {
        int e = g_order[start + i];
        int s = src[e];
        float etw = etw_tab[efeat[e]];

        const int4* fp = (const int4*)(g_fs16 + (size_t)s * 512 + kb);
        int4 fA = fp[0], fB = fp[1];
        const half2* h2a = (const half2*)&fA;
        const half2* h2b = (const half2*)&fB;

        float a = 0.f;
#pragma unroll
        for (int j = 0; j < 4; j++) {
            float2 v = __half22float2(h2a[j]);
            a += v.x * s_as[kb + 2 * j] + v.y * s_as[kb + 2 * j + 1];
        }
#pragma unroll
        for (int j = 0; j < 4; j++) {
            float2 v = __half22float2(h2b[j]);
            a += v.x * s_as[kb + 8 + 2 * j] + v.y * s_as[kb + 8 + 2 * j + 1];
        }
        a += __shfl_xor_sync(0xffffffffu, a, 1);
        a += __shfl_xor_sync(0xffffffffu, a, 2);

        float2 svf = __half22float2(((const half2*)(g_sn16 + (size_t)s * 64))[lane]);
        float2 tvf = __half22float2(((const half2*)(g_tn16 + (size_t)s * 64))[lane]);
        float cs = svf.x * s_sd[2 * lane] + svf.y * s_sd[2 * lane + 1];
        float ct = tvf.x * s_td[2 * lane] + tvf.y * s_td[2 * lane + 1];
#pragma unroll
        for (int off = 16; off; off >>= 1) {
            cs += __shfl_xor_sync(0xffffffffu, cs, off);
            ct += __shfl_xor_sync(0xffffffffu, ct, off);
        }
        float sim = (TAOV * cs + (1.f - TAOV) * ct + 1.f) * 0.5f;
        float ev = sim * a * etw;

        float mnew = fmaxf(m, ev);
        float ex = __expf(ev - mnew);
        if (ev > m) {
            float so = __expf(m - mnew);
            dsum *= so;
#pragma unroll
            for (int k = 0; k < 16; k++) { accR[k] *= so; accS[k] *= so; accT[k] *= so; }
            m = mnew;
        }
        dsum += ex;

#pragma unroll
        for (int j = 0; j < 4; j++) {
            float2 v = __half22float2(h2a[j]);
            accR[2 * j]     += ex * v.x;
            accR[2 * j + 1] += ex * v.y;
        }
#pragma unroll
        for (int j = 0; j < 4; j++) {
            float2 v = __half22float2(h2b[j]);
            accR[8 + 2 * j]     += ex * v.x;
            accR[8 + 2 * j + 1] += ex * v.y;
        }

        float exs = ex * g_snorm[s];
        float ext = ex * g_tnorm[s];
        const int4* sp = (const int4*)(g_sn16 + (size_t)s * 64 + d0);
        int4 s0 = sp[0], s1 = sp[1];
        const int4* tp = (const int4*)(g_tn16 + (size_t)s * 64 + d0);
        int4 t0 = tp[0], t1 = tp[1];
        const half2* sh0 = (const half2*)&s0; const half2* sh1 = (const half2*)&s1;
        const half2* th0 = (const half2*)&t0; const half2* th1 = (const half2*)&t1;
#pragma unroll
        for (int j = 0; j < 4; j++) {
            float2 v = __half22float2(sh0[j]); accS[2 * j] += exs * v.x; accS[2 * j + 1] += exs * v.y;
            float2 w = __half22float2(sh1[j]); accS[8 + 2 * j] += exs * w.x; accS[8 + 2 * j + 1] += exs * w.y;
            float2 x = __half22float2(th0[j]); accT[2 * j] += ext * x.x; accT[2 * j + 1] += ext * x.y;
            float2 y = __half22float2(th1[j]); accT[8 + 2 * j] += ext * y.x; accT[8 + 2 * j + 1] += ext * y.y;
        }
    }

    if (q == 0) s_wmax[warp * 8 + h] = m;
    __syncthreads();
    if (tid < 8) {
        float mm = -1e30f;
#pragma unroll
        for (int w = 0; w < 8; w++) mm = fmaxf(mm, s_wmax[w * 8 + tid]);
        s_gmax[tid] = mm;
    }
    __syncthreads();
    float sc = __expf(m - s_gmax[h]);
    if (q == 0) atomicAdd(&s_den[h], dsum * sc);
#pragma unroll
    for (int k = 0; k < 16; k++) {
        atomicAdd(&s_accR[kb + k], accR[k] * sc);
        atomicAdd(&s_accS[kb + k], accS[k] * sc);
        atomicAdd(&s_accT[kb + k], accT[k] * sc);
    }
    __syncthreads();

    // epilogue
    if (tid < 64) {
        int d = tid;
        float rsum = 0.f, ssum = 0.f, tsum = 0.f;
#pragma unroll
        for (int hh = 0; hh < 8; hh++) {
            float den = s_den[hh];
            float inv = (den > 0.f) ? (1.f / den) : 0.f;
            float r = s_accR[hh * 64 + d] * inv + g_res[n * 512 + hh * 64 + d];
            rsum += fmaxf(r, 0.f);
            ssum += s_accS[hh * 64 + d] * inv;
            tsum += s_accT[hh * 64 + d] * inv;
        }
        out[n * 64 + d]               = rsum * 0.125f;
        out[NN * 64 + n * 64 + d]     = sloc[n * 64 + d] + ssum * 0.125f;
        out[2 * NN * 64 + n * 64 + d] = topo[n * 64 + d] + tsum * 0.125f;
    }
}

// ------------------- launch -------------------
extern "C" void kernel_launch(void* const* d_in, const int* in_sizes, int n_in,
                              void* d_out, int out_size) {
    const float* feat  = (const float*)d_in[0];
    const float* sloc  = (const float*)d_in[1];
    const float* topo  = (const float*)d_in[2];
    const float* Wp    = (const float*)d_in[3];
    const float* Wr    = (const float*)d_in[4];
    const float* Wprob = (const float*)d_in[5];
    const float* etw   = (const float*)d_in[6];
    const int*   src   = (const int*)d_in[7];
    const int*   dst   = (const int*)d_in[8];
    const int*   ef    = (const int*)d_in[9];
    float* out = (float*)d_out;
    int E = in_sizes[7];
    if (E > EMAX) E = EMAX;

    k_zero<<<7, 256>>>();
    k_gemm<<<dim3(8, 13), 256>>>(feat, Wp, Wr);
    k_attn<<<64, 256>>>(Wprob);
    k_colsq<<<dim3(2, 64), 256>>>();
    k_rscale<<<2, 256>>>();
    k_rownorm<<<(NN + 3) / 4, 128>>>(sloc, topo);
    k_hist<<<(E + 255) / 256, 256>>>(dst, E);
    k_scan<<<1, 512>>>();
    k_scatter<<<(E + 255) / 256, 256>>>(dst, E);
    k_edge<<<NN, 256>>>(sloc, topo, etw, src, ef, out);
}

// round 6
// speedup vs baseline: 1.0128x; 1.0128x over previous
#include <cuda_runtime.h>
#include <cuda_fp16.h>
#include <cstdint>

#define NN   1546
#define ND   1373
#define KF   1546
#define HEADS 8
#define EMAX 210000
#define EPSV 1e-12f
#define TAOV 0.4f

// ------------------- scratch (device globals; no allocs allowed) -------------------
__device__ __align__(16) float  g_fs  [NN * 512];   // feat_src  [N, 8*64] fp32
__device__ __align__(16) __half g_fs16[NN * 512];   // feat_src fp16 (edge phase)
__device__ __align__(16) float  g_res [NN * 512];   // resval
__device__ __align__(16) float  g_attn[NN * 512];   // ft_attn
__device__ __align__(16) __half g_sn16[NN * 64];    // sloc normalized, fp16
__device__ __align__(16) __half g_tn16[NN * 64];    // topo normalized, fp16
__device__ float g_snorm[NN];
__device__ float g_tnorm[NN];
__device__ float g_colsq [512];
__device__ float g_rscale[512];
__device__ int   g_cnt[NN];
__device__ int   g_off[NN];
__device__ int   g_cur[NN];
__device__ int   g_order[EMAX];

// ------------------- helpers -------------------
__device__ __forceinline__ void mma_f16(float* c, const uint32_t* a, const uint32_t* b) {
    asm volatile(
        "mma.sync.aligned.m16n8k16.row.col.f32.f16.f16.f32 "
        "{%0,%1,%2,%3}, {%4,%5,%6,%7}, {%8,%9}, {%0,%1,%2,%3};\n"
        : "+f"(c[0]), "+f"(c[1]), "+f"(c[2]), "+f"(c[3])
        : "r"(a[0]), "r"(a[1]), "r"(a[2]), "r"(a[3]), "r"(b[0]), "r"(b[1]));
}

// ------------------- zero scratch counters -------------------
__global__ void k_zero() {
    int i = blockIdx.x * 256 + threadIdx.x;
    if (i < NN)  g_cnt[i] = 0;
    if (i < 512) g_colsq[i] = 0.f;
}

// ------------------- fp16 GEMM: BM=128 BN=128 BK=16, 256 thr, warp tile 32x64 -------------------
#define APADH 24   // halves per A row (16 used)
#define BPADH 18   // halves per B row (16 used), B stored transposed [n][k]

// A loads: float2 granularity — KF=1546 is 2 mod 4, so float4 would misalign on odd rows.
__device__ __forceinline__ void ldA2(const float* feat, int rowb, int rowEnd, int k0,
                                     int tid, float2* pa) {
#pragma unroll
    for (int j = 0; j < 4; j++) {
        int idx = tid + j * 256;
        int r = idx >> 3, c2 = idx & 7;
        int gr = rowb + r, gk = k0 + c2 * 2;
        float2 v = make_float2(0.f, 0.f);
        if (gr < rowEnd) {
            const float* p = feat + (size_t)gr * KF + gk;
            if (gk + 2 <= KF)      v = *(const float2*)p;
            else if (gk < KF)      v.x = *p;
        }
        pa[j] = v;
    }
}
__device__ __forceinline__ void ldB2(const float* W, int colb, int k0, int tid, float4* pb) {
#pragma unroll
    for (int j = 0; j < 2; j++) {
        int idx = tid + j * 256;
        int r = idx >> 5, c4 = idx & 31;
        int gk = k0 + r;
        float4 v = make_float4(0.f, 0.f, 0.f, 0.f);
        if (gk < KF) v = *(const float4*)(W + (size_t)gk * 512 + colb + c4 * 4);
        pb[j] = v;
    }
}
__device__ __forceinline__ void stA2(__half* As, int tid, const float2* pa) {
#pragma unroll
    for (int j = 0; j < 4; j++) {
        int idx = tid + j * 256;
        int r = idx >> 3, c2 = idx & 7;
        *(half2*)(As + r * APADH + c2 * 2) = __floats2half2_rn(pa[j].x, pa[j].y);
    }
}
__device__ __forceinline__ void stB2(__half* Bs, int tid, const float4* pb) {
#pragma unroll
    for (int j = 0; j < 2; j++) {
        int idx = tid + j * 256;
        int r = idx >> 5, c4 = idx & 31;
        int n0 = c4 * 4;
        Bs[(n0 + 0) * BPADH + r] = __float2half_rn(pb[j].x);
        Bs[(n0 + 1) * BPADH + r] = __float2half_rn(pb[j].y);
        Bs[(n0 + 2) * BPADH + r] = __float2half_rn(pb[j].z);
        Bs[(n0 + 3) * BPADH + r] = __float2half_rn(pb[j].w);
    }
}

__global__ __launch_bounds__(256, 1) void k_gemm(const float* __restrict__ feat,
                                                 const float* __restrict__ Wp,
                                                 const float* __restrict__ Wr) {
    __shared__ __align__(16) __half As[2][128 * APADH];
    __shared__ __align__(16) __half Bs[2][128 * BPADH];
    int tid = threadIdx.x, lane = tid & 31, warp = tid >> 5;
    int by = blockIdx.y, bx = blockIdx.x;

    int g, rowb, rowEnd;
    if (by < 11) { g = 0; rowb = by * 128; rowEnd = ND; }
    else         { g = 1; rowb = ND + (by - 11) * 128; rowEnd = NN; }

    int cb0 = bx * 128;
    const float* W;
    float* outp;
    int colb;
    bool isFs;
    if (cb0 < 512) { W = Wp + (size_t)g * KF * 512; outp = g_fs;  colb = cb0;       isFs = true; }
    else           { W = Wr + (size_t)g * KF * 512; outp = g_res; colb = cb0 - 512; isFs = false; }

    float c[2][8][4];
#pragma unroll
    for (int i = 0; i < 2; i++)
#pragma unroll
        for (int j = 0; j < 8; j++)
#pragma unroll
            for (int k = 0; k < 4; k++) c[i][j][k] = 0.f;

    float2 pa[4];
    float4 pb[2];
    ldA2(feat, rowb, rowEnd, 0, tid, pa);
    ldB2(W, colb, 0, tid, pb);
    stA2(As[0], tid, pa);
    stB2(Bs[0], tid, pb);
    __syncthreads();

    int p = 0;
    int warpM = warp >> 1, warpN = warp & 1;
    int t2 = (lane & 3) * 2;
    for (int k0 = 0; k0 < KF; k0 += 16) {
        int kn = k0 + 16;
        if (kn < KF) { ldA2(feat, rowb, rowEnd, kn, tid, pa); ldB2(W, colb, kn, tid, pb); }

        uint32_t af[2][4], bf[8][2];
#pragma unroll
        for (int mt = 0; mt < 2; mt++) {
            int row = warpM * 32 + mt * 16 + (lane >> 2);
            af[mt][0] = *(const uint32_t*)&As[p][row * APADH + t2];
            af[mt][1] = *(const uint32_t*)&As[p][(row + 8) * APADH + t2];
            af[mt][2] = *(const uint32_t*)&As[p][row * APADH + t2 + 8];
            af[mt][3] = *(const uint32_t*)&As[p][(row + 8) * APADH + t2 + 8];
        }
#pragma unroll
        for (int nt = 0; nt < 8; nt++) {
            int col = warpN * 64 + nt * 8 + (lane >> 2);
            bf[nt][0] = *(const uint32_t*)&Bs[p][col * BPADH + t2];
            bf[nt][1] = *(const uint32_t*)&Bs[p][col * BPADH + t2 + 8];
        }
#pragma unroll
        for (int mt = 0; mt < 2; mt++)
#pragma unroll
            for (int nt = 0; nt < 8; nt++)
                mma_f16(c[mt][nt], af[mt], bf[nt]);

        if (kn < KF) {
            stA2(As[p ^ 1], tid, pa);
            stB2(Bs[p ^ 1], tid, pb);
            __syncthreads();
            p ^= 1;
        }
    }

#pragma unroll
    for (int mt = 0; mt < 2; mt++) {
        int row0 = rowb + warpM * 32 + mt * 16 + (lane >> 2);
#pragma unroll
        for (int nt = 0; nt < 8; nt++) {
            int col = colb + warpN * 64 + nt * 8 + (lane & 3) * 2;
            if (row0 < rowEnd) {
                *(float2*)(outp + (size_t)row0 * 512 + col) = make_float2(c[mt][nt][0], c[mt][nt][1]);
                if (isFs)
                    *(half2*)(g_fs16 + (size_t)row0 * 512 + col) = __floats2half2_rn(c[mt][nt][0], c[mt][nt][1]);
            }
            if (row0 + 8 < rowEnd) {
                *(float2*)(outp + (size_t)(row0 + 8) * 512 + col) = make_float2(c[mt][nt][2], c[mt][nt][3]);
                if (isFs)
                    *(half2*)(g_fs16 + (size_t)(row0 + 8) * 512 + col) = __floats2half2_rn(c[mt][nt][2], c[mt][nt][3]);
            }
        }
    }
}

// ------------------- ft_attn = softmax(tanh(fs @ Wprob[h])), Wprob cached in smem -------------------
#define ATTN_CH 194
__global__ __launch_bounds__(256) void k_attn(const float* __restrict__ Wprob) {
    __shared__ float Wh[4096];
    __shared__ float fsh[8][64];
    int tid = threadIdx.x, warp = tid >> 5, lane = tid & 31;
    int h = blockIdx.x & 7, chunk = blockIdx.x >> 3;
    const float* W = Wprob + h * 4096;
    for (int i = tid; i < 4096; i += 256) Wh[i] = W[i];
    __syncthreads();

    int n0 = chunk * ATTN_CH;
    int n1 = min(n0 + ATTN_CH, NN);
    for (int n = n0 + warp; n < n1; n += 8) {
        fsh[warp][lane]      = g_fs[n * 512 + h * 64 + lane];
        fsh[warp][lane + 32] = g_fs[n * 512 + h * 64 + lane + 32];
        __syncwarp();
        float a0 = 0.f, a1 = 0.f;
#pragma unroll 8
        for (int d = 0; d < 64; d++) {
            float f = fsh[warp][d];
            a0 += f * Wh[d * 64 + lane];
            a1 += f * Wh[d * 64 + lane + 32];
        }
        float t0 = tanhf(a0), t1 = tanhf(a1);
        float m = fmaxf(t0, t1);
#pragma unroll
        for (int off = 16; off; off >>= 1) m = fmaxf(m, __shfl_xor_sync(0xffffffffu, m, off));
        float e0 = __expf(t0 - m), e1 = __expf(t1 - m);
        float s = e0 + e1;
#pragma unroll
        for (int off = 16; off; off >>= 1) s += __shfl_xor_sync(0xffffffffu, s, off);
        float inv = 1.f / s;
        g_attn[n * 512 + h * 64 + lane]      = e0 * inv;
        g_attn[n * 512 + h * 64 + lane + 32] = e1 * inv;
        __syncwarp();
    }
}

// ------------------- column sq-sums of fs (axis-0 L2 norm) -------------------
__global__ void k_colsq() {
    int c = blockIdx.x * 256 + threadIdx.x;           // gridDim = (2, 64)
    int r0 = blockIdx.y * 25;
    int r1 = min(r0 + 25, NN);
    float acc = 0.f;
    for (int n = r0; n < r1; n++) {
        float v = g_fs[n * 512 + c];
        acc += v * v;
    }
    atomicAdd(&g_colsq[c], acc);
}
__global__ void k_rscale() {
    int c = blockIdx.x * 256 + threadIdx.x;
    if (c < 512) g_rscale[c] = 1.f / fmaxf(sqrtf(g_colsq[c]), EPSV);
}

// ------------------- row norms of sloc / topo -> normalized fp16 + norms -------------------
__global__ __launch_bounds__(128) void k_rownorm(const float* __restrict__ sloc,
                                                 const float* __restrict__ topo) {
    int warp = threadIdx.x >> 5, lane = threadIdx.x & 31;
    int n = blockIdx.x * 4 + warp;
    if (n >= NN) return;
    float2 sv = *(const float2*)(sloc + (size_t)n * 64 + 2 * lane);
    float2 tv = *(const float2*)(topo + (size_t)n * 64 + 2 * lane);
    float ss = sv.x * sv.x + sv.y * sv.y;
    float tt = tv.x * tv.x + tv.y * tv.y;
#pragma unroll
    for (int off = 16; off; off >>= 1) {
        ss += __shfl_xor_sync(0xffffffffu, ss, off);
        tt += __shfl_xor_sync(0xffffffffu, tt, off);
    }
    float sn = fmaxf(sqrtf(ss), EPSV), tn = fmaxf(sqrtf(tt), EPSV);
    float si = 1.f / sn, ti = 1.f / tn;
    ((half2*)(g_sn16 + (size_t)n * 64))[lane] = __floats2half2_rn(sv.x * si, sv.y * si);
    ((half2*)(g_tn16 + (size_t)n * 64))[lane] = __floats2half2_rn(tv.x * ti, tv.y * ti);
    if (lane == 0) { g_snorm[n] = sn; g_tnorm[n] = tn; }
}

// ------------------- counting sort of edges by dst -------------------
__global__ void k_hist(const int* __restrict__ dst, int E) {
    int e = blockIdx.x * 256 + threadIdx.x;
    if (e < E) atomicAdd(&g_cnt[dst[e]], 1);
}
__global__ __launch_bounds__(512) void k_scan() {
    __shared__ int sh[512];
    int t = threadIdx.x;
    int base = t * 4;
    int v0 = (base     < NN) ? g_cnt[base]     : 0;
    int v1 = (base + 1 < NN) ? g_cnt[base + 1] : 0;
    int v2 = (base + 2 < NN) ? g_cnt[base + 2] : 0;
    int v3 = (base + 3 < NN) ? g_cnt[base + 3] : 0;
    int p0 = v0, p1 = p0 + v1, p2 = p1 + v2, p3 = p2 + v3;
    sh[t] = p3;
    __syncthreads();
    for (int off = 1; off < 512; off <<= 1) {
        int x = 0;
        if (t >= off) x = sh[t - off];
        __syncthreads();
        sh[t] += x;
        __syncthreads();
    }
    int excl = sh[t] - p3;
    if (base     < NN) { g_off[base]     = excl;      g_cur[base]     = excl; }
    if (base + 1 < NN) { g_off[base + 1] = excl + p0; g_cur[base + 1] = excl + p0; }
    if (base + 2 < NN) { g_off[base + 2] = excl + p1; g_cur[base + 2] = excl + p1; }
    if (base + 3 < NN) { g_off[base + 3] = excl + p2; g_cur[base + 3] = excl + p2; }
}
__global__ void k_scatter(const int* __restrict__ dst, int E) {
    int e = blockIdx.x * 256 + threadIdx.x;
    if (e < E) {
        int pos = atomicAdd(&g_cur[dst[e]], 1);
        g_order[pos] = e;
    }
}

// ------------------- edge phase: single pass, online softmax, fp16 gathers -------------------
__global__ __launch_bounds__(256, 2) void k_edge(const float* __restrict__ sloc,
                                                 const float* __restrict__ topo,
                                                 const float* __restrict__ etw_tab,
                                                 const int* __restrict__ src,
                                                 const int* __restrict__ efeat,
                                                 float* __restrict__ out) {
    __shared__ float s_as[512];      // attn[dst] * rscale
    __shared__ float s_sd[64], s_td[64];
    __shared__ float s_accR[512], s_accS[512], s_accT[512];
    __shared__ float s_gmax[8], s_den[8], s_wmax[64];

    int n = blockIdx.x;
    int tid = threadIdx.x, warp = tid >> 5, lane = tid & 31;
    int start = g_off[n], cnt = g_cnt[n];

    for (int i = tid; i < 512; i += 256) {
        s_as[i] = g_attn[n * 512 + i] * g_rscale[i];
        s_accR[i] = 0.f; s_accS[i] = 0.f; s_accT[i] = 0.f;
    }
    if (tid < 64) {
        s_sd[tid] = __half2float(g_sn16[n * 64 + tid]);
        s_td[tid] = __half2float(g_tn16[n * 64 + tid]);
    }
    if (tid < 8) s_den[tid] = 0.f;
    __syncthreads();

    int h = lane >> 2, q = lane & 3;
    int kb = lane * 16, d0 = q * 16;
    float m = -1e30f, dsum = 0.f;
    float accR[16], accS[16], accT[16];
#pragma unroll
    for (int k = 0; k < 16; k++) { accR[k] = 0.f; accS[k] = 0.f; accT[k] = 0.f; }

    for (int i = warp; i < cnt; i += 8) {
        int e = g_order[start + i];
        int s = src[e];
        float etw = etw_tab[efeat[e]];

        const int4* fp = (const int4*)(g_fs16 + (size_t)s * 512 + kb);
        int4 fA = fp[0], fB = fp[1];
        const half2* h2a = (const half2*)&fA;
        const half2* h2b = (const half2*)&fB;

        float a = 0.f;
#pragma unroll
        for (int j = 0; j < 4; j++) {
            float2 v = __half22float2(h2a[j]);
            a += v.x * s_as[kb + 2 * j] + v.y * s_as[kb + 2 * j + 1];
        }
#pragma unroll
        for (int j = 0; j < 4; j++) {
            float2 v = __half22float2(h2b[j]);
            a += v.x * s_as[kb + 8 + 2 * j] + v.y * s_as[kb + 8 + 2 * j + 1];
        }
        a += __shfl_xor_sync(0xffffffffu, a, 1);
        a += __shfl_xor_sync(0xffffffffu, a, 2);

        float2 svf = __half22float2(((const half2*)(g_sn16 + (size_t)s * 64))[lane]);
        float2 tvf = __half22float2(((const half2*)(g_tn16 + (size_t)s * 64))[lane]);
        float cs = svf.x * s_sd[2 * lane] + svf.y * s_sd[2 * lane + 1];
        float ct = tvf.x * s_td[2 * lane] + tvf.y * s_td[2 * lane + 1];
#pragma unroll
        for (int off = 16; off; off >>= 1) {
            cs += __shfl_xor_sync(0xffffffffu, cs, off);
            ct += __shfl_xor_sync(0xffffffffu, ct, off);
        }
        float sim = (TAOV * cs + (1.f - TAOV) * ct + 1.f) * 0.5f;
        float ev = sim * a * etw;

        float mnew = fmaxf(m, ev);
        float ex = __expf(ev - mnew);
        if (ev > m) {
            float so = __expf(m - mnew);
            dsum *= so;
#pragma unroll
            for (int k = 0; k < 16; k++) { accR[k] *= so; accS[k] *= so; accT[k] *= so; }
            m = mnew;
        }
        dsum += ex;

#pragma unroll
        for (int j = 0; j < 4; j++) {
            float2 v = __half22float2(h2a[j]);
            accR[2 * j]     += ex * v.x;
            accR[2 * j + 1] += ex * v.y;
        }
#pragma unroll
        for (int j = 0; j < 4; j++) {
            float2 v = __half22float2(h2b[j]);
            accR[8 + 2 * j]     += ex * v.x;
            accR[8 + 2 * j + 1] += ex * v.y;
        }

        float exs = ex * g_snorm[s];
        float ext = ex * g_tnorm[s];
        const int4* sp = (const int4*)(g_sn16 + (size_t)s * 64 + d0);
        int4 s0 = sp[0], s1 = sp[1];
        const int4* tp = (const int4*)(g_tn16 + (size_t)s * 64 + d0);
        int4 t0 = tp[0], t1 = tp[1];
        const half2* sh0 = (const half2*)&s0; const half2* sh1 = (const half2*)&s1;
        const half2* th0 = (const half2*)&t0; const half2* th1 = (const half2*)&t1;
#pragma unroll
        for (int j = 0; j < 4; j++) {
            float2 v = __half22float2(sh0[j]); accS[2 * j] += exs * v.x; accS[2 * j + 1] += exs * v.y;
            float2 w = __half22float2(sh1[j]); accS[8 + 2 * j] += exs * w.x; accS[8 + 2 * j + 1] += exs * w.y;
            float2 x = __half22float2(th0[j]); accT[2 * j] += ext * x.x; accT[2 * j + 1] += ext * x.y;
            float2 y = __half22float2(th1[j]); accT[8 + 2 * j] += ext * y.x; accT[8 + 2 * j + 1] += ext * y.y;
        }
    }

    if (q == 0) s_wmax[warp * 8 + h] = m;
    __syncthreads();
    if (tid < 8) {
        float mm = -1e30f;
#pragma unroll
        for (int w = 0; w < 8; w++) mm = fmaxf(mm, s_wmax[w * 8 + tid]);
        s_gmax[tid] = mm;
    }
    __syncthreads();
    float sc = __expf(m - s_gmax[h]);
    if (q == 0) atomicAdd(&s_den[h], dsum * sc);
#pragma unroll
    for (int k = 0; k < 16; k++) {
        atomicAdd(&s_accR[kb + k], accR[k] * sc);
        atomicAdd(&s_accS[kb + k], accS[k] * sc);
        atomicAdd(&s_accT[kb + k], accT[k] * sc);
    }
    __syncthreads();

    // epilogue
    if (tid < 64) {
        int d = tid;
        float rsum = 0.f, ssum = 0.f, tsum = 0.f;
#pragma unroll
        for (int hh = 0; hh < 8; hh++) {
            float den = s_den[hh];
            float inv = (den > 0.f) ? (1.f / den) : 0.f;
            float r = s_accR[hh * 64 + d] * inv + g_res[n * 512 + hh * 64 + d];
            rsum += fmaxf(r, 0.f);
            ssum += s_accS[hh * 64 + d] * inv;
            tsum += s_accT[hh * 64 + d] * inv;
        }
        out[n * 64 + d]               = rsum * 0.125f;
        out[NN * 64 + n * 64 + d]     = sloc[n * 64 + d] + ssum * 0.125f;
        out[2 * NN * 64 + n * 64 + d] = topo[n * 64 + d] + tsum * 0.125f;
    }
}

// ------------------- launch -------------------
extern "C" void kernel_launch(void* const* d_in, const int* in_sizes, int n_in,
                              void* d_out, int out_size) {
    const float* feat  = (const float*)d_in[0];
    const float* sloc  = (const float*)d_in[1];
    const float* topo  = (const float*)d_in[2];
    const float* Wp    = (const float*)d_in[3];
    const float* Wr    = (const float*)d_in[4];
    const float* Wprob = (const float*)d_in[5];
    const float* etw   = (const float*)d_in[6];
    const int*   src   = (const int*)d_in[7];
    const int*   dst   = (const int*)d_in[8];
    const int*   ef    = (const int*)d_in[9];
    float* out = (float*)d_out;
    int E = in_sizes[7];
    if (E > EMAX) E = EMAX;

    k_zero<<<7, 256>>>();
    k_gemm<<<dim3(8, 13), 256>>>(feat, Wp, Wr);
    k_attn<<<64, 256>>>(Wprob);
    k_colsq<<<dim3(2, 64), 256>>>();
    k_rscale<<<2, 256>>>();
    k_rownorm<<<(NN + 3) / 4, 128>>>(sloc, topo);
    k_hist<<<(E + 255) / 256, 256>>>(dst, E);
    k_scan<<<1, 512>>>();
    k_scatter<<<(E + 255) / 256, 256>>>(dst, E);
    k_edge<<<NN, 256>>>(sloc, topo, etw, src, ef, out);
}